// round 4
// baseline (speedup 1.0000x reference)
#include <cuda_runtime.h>

// Perona-Malik single diffusion step — rolling-register strip kernel.
// One block = 32-row strip. Software-pipelined: prefetch next 4 rows while
// computing current 4 from registers. Shuffle halos, streaming stores.
// out = clamp(image + g * exp(-g^2/K^2) * dt, 0, 1)
// g   = 5-point Laplacian with ReflectionPad2d(1); K=0.1 (1/K^2=100), dt=0.15

#define W 1024
#define H 1024
#define W4 (W / 4)
#define STRIP 32           // rows per block
#define CHUNK 4            // rows per pipeline stage

__device__ __forceinline__ void stcs4(float4* p, float4 v) {
    asm volatile("st.global.cs.v4.f32 [%0], {%1,%2,%3,%4};"
                 :: "l"(p), "f"(v.x), "f"(v.y), "f"(v.z), "f"(v.w) : "memory");
}

__device__ __forceinline__ int reflect_row(int yy) {
    // ReflectionPad2d semantics (no edge duplication): -1 -> 1, H -> H-2, ...
    yy = (yy < 0) ? -yy : yy;
    yy = (yy >= H) ? (2 * H - 2 - yy) : yy;
    return yy;
}

__global__ __launch_bounds__(256, 4)
void pm_kernel(const float* __restrict__ in, float* __restrict__ out) {
    const int y0 = blockIdx.x * STRIP;     // first output row of this strip
    const int n  = blockIdx.y;             // image index
    const int t  = threadIdx.x;            // float4 column 0..255
    const int lane = t & 31;

    const float* img = in  + (size_t)n * (W * H);
    float*       o   = out + (size_t)n * (W * H);

    // Prologue: rows y0-1 .. y0+4 into cur[0..5].
    float4 cur[CHUNK + 2];
    #pragma unroll
    for (int i = 0; i < CHUNK + 2; i++) {
        const int yy = reflect_row(y0 - 1 + i);
        cur[i] = ((const float4*)(img + (size_t)yy * W))[t];
    }

    #pragma unroll
    for (int c = 0; c < STRIP; c += CHUNK) {
        // ── Prefetch rows y0+c+5 .. y0+c+8 (consumed next iteration) ──
        float4 nxt[CHUNK];
        #pragma unroll
        for (int j = 0; j < CHUNK; j++) {
            const int yy = reflect_row(y0 + c + CHUNK + 1 + j);
            nxt[j] = ((const float4*)(img + (size_t)yy * W))[t];
        }

        // ── Compute + store rows y0+c .. y0+c+3 from cur registers ──
        #pragma unroll
        for (int i = 0; i < CHUNK; i++) {
            const int y = y0 + c + i;
            const float4 u = cur[i];
            const float4 cc = cur[i + 1];
            const float4 d = cur[i + 2];

            // Horizontal halo: warp shuffle; warp-edge lanes fall back to a
            // scalar global load (L1 hit); image-edge lanes use reflection.
            float left  = __shfl_up_sync(0xffffffffu, cc.w, 1);
            float right = __shfl_down_sync(0xffffffffu, cc.x, 1);
            const float* rowc = img + (size_t)y * W;
            if (lane == 0)
                left  = (t == 0)      ? cc.y : rowc[4 * t - 1];
            if (lane == 31)
                right = (t == W4 - 1) ? cc.z : rowc[4 * t + 4];

            float4 g;
            g.x = u.x + d.x + left + cc.y  - 4.0f * cc.x;
            g.y = u.y + d.y + cc.x + cc.z  - 4.0f * cc.y;
            g.z = u.z + d.z + cc.y + cc.w  - 4.0f * cc.z;
            g.w = u.w + d.w + cc.z + right - 4.0f * cc.w;

            float4 r;
            float gg, co, v;
            gg = g.x; co = __expf(-gg * gg * 100.0f);
            v = fmaf(gg * co, 0.15f, cc.x); r.x = fminf(fmaxf(v, 0.0f), 1.0f);
            gg = g.y; co = __expf(-gg * gg * 100.0f);
            v = fmaf(gg * co, 0.15f, cc.y); r.y = fminf(fmaxf(v, 0.0f), 1.0f);
            gg = g.z; co = __expf(-gg * gg * 100.0f);
            v = fmaf(gg * co, 0.15f, cc.z); r.z = fminf(fmaxf(v, 0.0f), 1.0f);
            gg = g.w; co = __expf(-gg * gg * 100.0f);
            v = fmaf(gg * co, 0.15f, cc.w); r.w = fminf(fmaxf(v, 0.0f), 1.0f);

            stcs4((float4*)(o + (size_t)y * W) + t, r);
        }

        // ── Rotate: cur[i] <- row (y0+c+3)+i  (renamed away by full unroll) ──
        cur[0] = cur[4];
        cur[1] = cur[5];
        #pragma unroll
        for (int j = 0; j < CHUNK; j++)
            cur[j + 2] = nxt[j];
    }
}

extern "C" void kernel_launch(void* const* d_in, const int* in_sizes, int n_in,
                              void* d_out, int out_size) {
    const float* image = (const float*)d_in[0];
    // d_in[1] is the fixed 3x3 Laplace kernel; hardcoded in pm_kernel.
    float* out = (float*)d_out;

    const int n_images = in_sizes[0] / (W * H);   // 64
    dim3 grid(H / STRIP, n_images);
    pm_kernel<<<grid, 256>>>(image, out);
}

// round 5
// speedup vs baseline: 1.1724x; 1.1724x over previous
#include <cuda_runtime.h>

// Perona-Malik single diffusion step — ROWS=2 at max occupancy.
// 4 front-batched LDG.128/thread, shuffle halos, streaming stores.
// out = clamp(image + g * exp(-g^2/K^2) * dt, 0, 1)
// g   = 5-point Laplacian with ReflectionPad2d(1); K=0.1 (1/K^2=100), dt=0.15

#define W 1024
#define H 1024
#define W4 (W / 4)
#define ROWS 2

__device__ __forceinline__ void stcs4(float4* p, float4 v) {
    asm volatile("st.global.cs.v4.f32 [%0], {%1,%2,%3,%4};"
                 :: "l"(p), "f"(v.x), "f"(v.y), "f"(v.z), "f"(v.w) : "memory");
}

__global__ __launch_bounds__(256, 8)
void pm_kernel(const float* __restrict__ in, float* __restrict__ out) {
    const int y0 = blockIdx.x * ROWS;      // first output row of this block
    const int n  = blockIdx.y;             // image index
    const int t  = threadIdx.x;            // float4 column 0..255
    const int lane = t & 31;

    const float* img = in  + (size_t)n * (W * H);
    float*       o   = out + (size_t)n * (W * H);

    // Rows y0-1 .. y0+2, reflect at volume edges (no edge duplication):
    // -1 -> 1, H -> H-2. Front-batched: 4 consecutive LDG.128 per thread.
    float4 rr[ROWS + 2];
    #pragma unroll
    for (int i = 0; i < ROWS + 2; i++) {
        int yy = y0 - 1 + i;
        yy = (yy < 0) ? 1 : ((yy >= H) ? (2 * H - 2 - yy) : yy);
        rr[i] = ((const float4*)(img + (size_t)yy * W))[t];
    }

    const float* rowc = img + (size_t)y0 * W;
    float4*      po   = (float4*)(o + (size_t)y0 * W) + t;

    #pragma unroll
    for (int i = 0; i < ROWS; i++) {
        const float4 u = rr[i];
        const float4 c = rr[i + 1];
        const float4 d = rr[i + 2];

        // Horizontal halo via warp shuffle; warp-edge lanes fall back to a
        // scalar global load (L1 hit); image-edge lanes use reflection.
        float left  = __shfl_up_sync(0xffffffffu, c.w, 1);
        float right = __shfl_down_sync(0xffffffffu, c.x, 1);
        if (lane == 0)
            left  = (t == 0)      ? c.y : rowc[4 * t - 1];
        if (lane == 31)
            right = (t == W4 - 1) ? c.z : rowc[4 * t + 4];

        float4 g;
        g.x = u.x + d.x + left + c.y  - 4.0f * c.x;
        g.y = u.y + d.y + c.x  + c.z  - 4.0f * c.y;
        g.z = u.z + d.z + c.y  + c.w  - 4.0f * c.z;
        g.w = u.w + d.w + c.z  + right - 4.0f * c.w;

        float4 r;
        float gg, co, v;
        gg = g.x; co = __expf(-gg * gg * 100.0f);
        v = fmaf(gg * co, 0.15f, c.x); r.x = fminf(fmaxf(v, 0.0f), 1.0f);
        gg = g.y; co = __expf(-gg * gg * 100.0f);
        v = fmaf(gg * co, 0.15f, c.y); r.y = fminf(fmaxf(v, 0.0f), 1.0f);
        gg = g.z; co = __expf(-gg * gg * 100.0f);
        v = fmaf(gg * co, 0.15f, c.z); r.z = fminf(fmaxf(v, 0.0f), 1.0f);
        gg = g.w; co = __expf(-gg * gg * 100.0f);
        v = fmaf(gg * co, 0.15f, c.w); r.w = fminf(fmaxf(v, 0.0f), 1.0f);

        stcs4(po, r);
        po   += W4;
        rowc += W;
    }
}

extern "C" void kernel_launch(void* const* d_in, const int* in_sizes, int n_in,
                              void* d_out, int out_size) {
    const float* image = (const float*)d_in[0];
    // d_in[1] is the fixed 3x3 Laplace kernel; hardcoded in pm_kernel.
    float* out = (float*)d_out;

    const int n_images = in_sizes[0] / (W * H);   // 64
    dim3 grid(H / ROWS, n_images);
    pm_kernel<<<grid, 256>>>(image, out);
}